// round 4
// baseline (speedup 1.0000x reference)
#include <cuda_runtime.h>
#include <cuda_fp16.h>
#include <cstdint>
#include <cstddef>

#define N_NODES 10000
#define EMBED   300
#define HID     256

// big GEMM tiling: BM=80 x BN=128 per CTA, grid = 125 * 2 = 250 (one full wave,
// 2 CTAs/SM), BK=64 fp16 = one 128B SW128 row.
#define BM      80
#define BN      128
#define BK      64
#define NKCH    157       // ceil(10000/64)
#define STAGES  4

#define ADJ_SCALE  16384.0f          // lift adj out of fp16-subnormal range (2^14)
#define ADJ_INV    6.103515625e-05f  // 2^-14

// ---- dynamic smem layout for big GEMM ----
#define SM_BIAS   0                           // 256 floats
#define A_BYTES   (BM * BK * 2)               // 10240
#define B_BYTES   (BN * BK * 2)               // 16384
#define STG_BYTES (A_BYTES + B_BYTES)         // 26624 (26 KB, 1KB-aligned)
#define SM_A(s)   (1024 + (s) * STG_BYTES)
#define SM_B(s)   (SM_A(s) + A_BYTES)
#define SMEM_BYTES (1024 + STAGES * STG_BYTES)  // 107520 -> 2 CTAs/SM

// ---- device scratch (allocation-free rule: __device__ globals) ----
__device__ __align__(1024) __half g_adjh[(size_t)N_NODES * N_NODES]; // adj * 2^14, fp16
__device__ __align__(1024) float  g_x   [N_NODES * EMBED];           // gather+max result
__device__ __align__(1024) __half g_yTh [HID * N_NODES];             // (X@W)^T fp16, K-major B
__device__ __align__(1024) float  g_h1  [N_NODES * HID];             // layer-1 activations

// ---------------------------------------------------------------------------
static __device__ __forceinline__ uint32_t smem_u32(const void* p) {
    uint32_t a;
    asm("{ .reg .u64 t; cvta.to.shared.u64 t, %1; cvt.u32.u64 %0, t; }" : "=r"(a) : "l"(p));
    return a;
}
#define SWZ(b) ((b) ^ (((b) >> 3) & 0x70))

static __device__ __forceinline__ void cp_async16(uint32_t dst, const void* src, uint32_t nbytes) {
    asm volatile("cp.async.cg.shared.global [%0], [%1], 16, %2;"
        :: "r"(dst), "l"(src), "r"(nbytes) : "memory");
}
#define CP_COMMIT() asm volatile("cp.async.commit_group;" ::: "memory")

static __device__ __forceinline__ void ldsm_x4(uint32_t r[4], uint32_t addr) {
    asm volatile("ldmatrix.sync.aligned.m8n8.x4.shared.b16 {%0,%1,%2,%3}, [%4];"
        : "=r"(r[0]), "=r"(r[1]), "=r"(r[2]), "=r"(r[3]) : "r"(addr));
}
static __device__ __forceinline__ void mma16816(float c[4], const uint32_t a[4],
                                                uint32_t b0, uint32_t b1) {
    asm volatile("mma.sync.aligned.m16n8k16.row.col.f32.f16.f16.f32 "
        "{%0,%1,%2,%3}, {%4,%5,%6,%7}, {%8,%9}, {%0,%1,%2,%3};"
        : "+f"(c[0]), "+f"(c[1]), "+f"(c[2]), "+f"(c[3])
        : "r"(a[0]), "r"(a[1]), "r"(a[2]), "r"(a[3]), "r"(b0), "r"(b1));
}

// ---------------------------------------------------------------------------
// Kernel 0: adj (fp32) -> g_adjh (fp16, scaled by 2^14). 8 elems/thread.
// ---------------------------------------------------------------------------
__global__ void __launch_bounds__(256) convert_adj_kernel(const float* __restrict__ adj) {
    size_t i = ((size_t)blockIdx.x * 256 + threadIdx.x) * 8;
    if (i >= (size_t)N_NODES * N_NODES) return;
    float4 v0 = *(const float4*)(adj + i);
    float4 v1 = *(const float4*)(adj + i + 4);
    __half2 h[4];
    h[0] = __floats2half2_rn(v0.x * ADJ_SCALE, v0.y * ADJ_SCALE);
    h[1] = __floats2half2_rn(v0.z * ADJ_SCALE, v0.w * ADJ_SCALE);
    h[2] = __floats2half2_rn(v1.x * ADJ_SCALE, v1.y * ADJ_SCALE);
    h[3] = __floats2half2_rn(v1.z * ADJ_SCALE, v1.w * ADJ_SCALE);
    *(uint4*)(g_adjh + i) = *(uint4*)h;
}

// ---------------------------------------------------------------------------
// Kernel 1: gather + max over REP=8 embeddings
// ---------------------------------------------------------------------------
__global__ void gather_max_kernel(const int* __restrict__ nodes, const float* __restrict__ emb) {
    int m = blockIdx.x;
    __shared__ int idx[8];
    if (threadIdx.x < 8) idx[threadIdx.x] = nodes[(m + 1) * 8 + threadIdx.x];
    __syncthreads();
    for (int e = threadIdx.x; e < EMBED / 4; e += blockDim.x) {
        float4 mx = *(const float4*)(emb + (size_t)idx[0] * EMBED + e * 4);
        #pragma unroll
        for (int r = 1; r < 8; ++r) {
            float4 v = *(const float4*)(emb + (size_t)idx[r] * EMBED + e * 4);
            mx.x = fmaxf(mx.x, v.x); mx.y = fmaxf(mx.y, v.y);
            mx.z = fmaxf(mx.z, v.z); mx.w = fmaxf(mx.w, v.w);
        }
        *(float4*)(g_x + (size_t)m * EMBED + e * 4) = mx;
    }
}

// ---------------------------------------------------------------------------
// Kernel 2: small GEMM (exact fp32):  g_yTh[n][m] = fp16_rn( (X @ W)[m][n] )
// ---------------------------------------------------------------------------
__global__ void __launch_bounds__(256) small_gemm_kernel(const float* __restrict__ W, int K, int layer) {
    __shared__ float xs[32][17];
    __shared__ float ws[16][256];
    const float* X = layer ? g_h1 : g_x;
    int ldx = layer ? HID : EMBED;
    int m0 = blockIdx.x * 32;
    int tid = threadIdx.x;
    int tr = tid >> 6, tc = tid & 63;
    float acc[8][4] = {};

    for (int k0 = 0; k0 < K; k0 += 16) {
        #pragma unroll
        for (int j = 0; j < 2; ++j) {
            int idx = tid + j * 256; int r = idx >> 4, c = idx & 15;
            int gm = m0 + r, gk = k0 + c;
            xs[r][c] = (gm < N_NODES && gk < K) ? X[(size_t)gm * ldx + gk] : 0.0f;
        }
        #pragma unroll
        for (int j = 0; j < 4; ++j) {
            int idx = tid + j * 256; int r = idx >> 6, c4 = idx & 63;
            float4 v = make_float4(0.f, 0.f, 0.f, 0.f);
            if (k0 + r < K) v = *(const float4*)(W + (size_t)(k0 + r) * HID + c4 * 4);
            *(float4*)&ws[r][c4 * 4] = v;
        }
        __syncthreads();
        #pragma unroll
        for (int kk = 0; kk < 16; ++kk) {
            float4 w = *(const float4*)&ws[kk][tc * 4];
            #pragma unroll
            for (int i = 0; i < 8; ++i) {
                float xv = xs[tr * 8 + i][kk];
                acc[i][0] += xv * w.x; acc[i][1] += xv * w.y;
                acc[i][2] += xv * w.z; acc[i][3] += xv * w.w;
            }
        }
        __syncthreads();
    }
    #pragma unroll
    for (int i = 0; i < 8; ++i) {
        int m = m0 + tr * 8 + i;
        if (m < N_NODES) {
            #pragma unroll
            for (int j = 0; j < 4; ++j)
                g_yTh[(size_t)(tc * 4 + j) * N_NODES + m] = __float2half_rn(acc[i][j]);
        }
    }
}

// ---------------------------------------------------------------------------
// Kernel 3: big GEMM via mma.sync (fp16 in, fp32 accum)
//   out[m][n] = leaky_relu( (sum_k adjh[m][k]*yTh[n][k]) * 2^-14 + bias[n] )
// BM=80 x BN=128 per CTA, 2 CTAs/SM, 4-stage cp.async.
// blockIdx.x: bit0 = N-half, bits 1.. = M-tile. 8 warps; warp w owns 16 cols.
// Warp tile 80x16: 5 m16-frags x 2 n8-frags, 40 accum regs.
// One barrier per chunk; fill issued immediately after it (before MMAs).
// ---------------------------------------------------------------------------
__global__ void __launch_bounds__(256, 2)
big_gemm_kernel(const float* __restrict__ bias, float* __restrict__ dout) {
    extern __shared__ char smem[];
    uint32_t sb = smem_u32(smem);
    int tid = threadIdx.x;
    int w = tid >> 5, lane = tid & 31;
    float* out = dout ? dout : g_h1;
    int m0    = (blockIdx.x >> 1) * BM;
    int nbase = (blockIdx.x & 1) * BN;

    ((float*)(smem + SM_BIAS))[tid] = bias[tid];

    float acc[5][2][4];
    #pragma unroll
    for (int a = 0; a < 5; ++a)
        #pragma unroll
        for (int b = 0; b < 2; ++b)
            #pragma unroll
            for (int c = 0; c < 4; ++c) acc[a][b][c] = 0.f;

    auto fill = [&](int chunk) {
        int s = chunk & (STAGES - 1);
        int k0 = chunk * BK;
        uint32_t sa = sb + SM_A(s), sB = sb + SM_B(s);
        // A: 80 rows x 8 chunks of 16B = 640 units
        #pragma unroll
        for (int i = 0; i < 3; ++i) {
            int c = tid + i * 256;
            if (c < 640) {
                int row = c >> 3, ch = c & 7;
                int kk = k0 + ch * 8;
                int ok = kk < N_NODES;
                const __half* g = g_adjh + (size_t)(m0 + row) * N_NODES + (ok ? kk : 0);
                cp_async16(sa + SWZ(row * 128 + ch * 16), g, ok ? 16u : 0u);
            }
        }
        // B: 128 rows x 8 chunks of 16B = 1024 units
        #pragma unroll
        for (int i = 0; i < 4; ++i) {
            int c = tid + i * 256;
            int row = c >> 3, ch = c & 7;
            int kk = k0 + ch * 8;
            int ok = kk < N_NODES;
            const __half* g = g_yTh + (size_t)(nbase + row) * N_NODES + (ok ? kk : 0);
            cp_async16(sB + SWZ(row * 128 + ch * 16), g, ok ? 16u : 0u);
        }
        CP_COMMIT();
    };

    // prologue: stages 0..2 (3 outstanding groups; steady state stays at 3)
    fill(0); fill(1); fill(2);

    for (int j = 0; j < NKCH; ++j) {
        asm volatile("cp.async.wait_group %0;" :: "n"(STAGES - 2));
        __syncthreads();
        // stage (j+3)&3 == (j-1)&3 was fully consumed before this barrier:
        // refill it now so cp.async latency overlaps the MMAs below.
        if (j + 3 < NKCH) fill(j + 3); else CP_COMMIT();

        int s = j & (STAGES - 1);
        uint32_t sa = sb + SM_A(s), sB = sb + SM_B(s);
        #pragma unroll
        for (int ks = 0; ks < 4; ++ks) {
            uint32_t af[5][4];
            #pragma unroll
            for (int mt = 0; mt < 5; ++mt) {
                uint32_t off = (uint32_t)(mt * 16 + (lane & 15)) * 128 + ks * 32 + (lane >> 4) * 16;
                ldsm_x4(af[mt], sa + SWZ(off));
            }
            uint32_t bf[4];
            {
                uint32_t row = w * 16 + ((lane >> 4) & 1) * 8 + (lane & 7);
                uint32_t off = row * 128 + ks * 32 + ((lane >> 3) & 1) * 16;
                ldsm_x4(bf, sB + SWZ(off));
            }
            #pragma unroll
            for (int mt = 0; mt < 5; ++mt)
                #pragma unroll
                for (int nt = 0; nt < 2; ++nt)
                    mma16816(acc[mt][nt], af[mt], bf[nt * 2], bf[nt * 2 + 1]);
        }
    }

    // ---- epilogue: unscale, bias, leaky_relu, store fp32 ----
    const float* bsm = (const float*)(smem + SM_BIAS);
    int qr = lane >> 2, qc = lane & 3;
    #pragma unroll
    for (int mt = 0; mt < 5; ++mt) {
        int r0 = m0 + mt * 16 + qr;
        #pragma unroll
        for (int nt = 0; nt < 2; ++nt) {
            int col = nbase + w * 16 + nt * 8 + qc * 2;
            float b0 = bsm[col], b1 = bsm[col + 1];
            float v0 = acc[mt][nt][0] * ADJ_INV + b0;
            float v1 = acc[mt][nt][1] * ADJ_INV + b1;
            float v2 = acc[mt][nt][2] * ADJ_INV + b0;
            float v3 = acc[mt][nt][3] * ADJ_INV + b1;
            float2 p0 = make_float2(fmaxf(v0, 0.01f * v0), fmaxf(v1, 0.01f * v1));
            float2 p1 = make_float2(fmaxf(v2, 0.01f * v2), fmaxf(v3, 0.01f * v3));
            *(float2*)&out[(size_t)r0 * HID + col]       = p0;
            *(float2*)&out[(size_t)(r0 + 8) * HID + col] = p1;
        }
    }
}

// ---------------------------------------------------------------------------
extern "C" void kernel_launch(void* const* d_in, const int* in_sizes, int n_in,
                              void* d_out, int out_size) {
    (void)in_sizes; (void)n_in; (void)out_size;
    const int*   nodes = (const int*)  d_in[0];
    const float* emb   = (const float*)d_in[1];
    const float* adj   = (const float*)d_in[2];
    const float* W1    = (const float*)d_in[3];
    const float* b1    = (const float*)d_in[4];
    const float* W2    = (const float*)d_in[5];
    const float* b2    = (const float*)d_in[6];
    float* out = (float*)d_out;

    cudaFuncSetAttribute(big_gemm_kernel, cudaFuncAttributeMaxDynamicSharedMemorySize, SMEM_BYTES);

    size_t total = (size_t)N_NODES * N_NODES;
    int cgrid = (int)((total / 8 + 255) / 256);
    int gs = (N_NODES + 31) / 32;       // 313
    int gm = (N_NODES / BM) * 2;        // 250, exact, one wave at 2 CTAs/SM

    convert_adj_kernel<<<cgrid, 256>>>(adj);
    gather_max_kernel<<<N_NODES, 128>>>(nodes, emb);
    small_gemm_kernel<<<gs, 256>>>(W1, EMBED, 0);
    big_gemm_kernel<<<gm, 256, SMEM_BYTES>>>(b1, nullptr);   // g_h1
    small_gemm_kernel<<<gs, 256>>>(W2, HID, 1);
    big_gemm_kernel<<<gm, 256, SMEM_BYTES>>>(b2, out);
}

// round 5
// speedup vs baseline: 1.0370x; 1.0370x over previous
#include <cuda_runtime.h>
#include <cuda_fp16.h>
#include <cstdint>
#include <cstddef>

#define N_NODES 10000
#define EMBED   300
#define HID     256

// big GEMM tiling: BM=80 x BN=256 per CTA, 125 CTAs (exact), 1 CTA/SM.
#define BM      80
#define BK      64
#define NKCH    157       // ceil(10000/64)
#define STAGES  4

#define ADJ_SCALE  16384.0f          // lift adj out of fp16-subnormal range (2^14)
#define ADJ_INV    6.103515625e-05f  // 2^-14

// ---- dynamic smem layout for big GEMM ----
#define SM_BIAS   0                           // 256 floats
#define A_BYTES   (BM  * BK * 2)              // 10240
#define B_BYTES   (256 * BK * 2)              // 32768
#define STG_BYTES (A_BYTES + B_BYTES)         // 43008
#define SM_A(s)   (1024 + (s) * STG_BYTES)
#define SM_B(s)   (SM_A(s) + A_BYTES)
#define SMEM_BYTES (1024 + STAGES * STG_BYTES)  // 173056

// ---- device scratch ----
__device__ __align__(1024) __half g_adjh[(size_t)N_NODES * N_NODES]; // adj * 2^14, fp16
__device__ __align__(1024) float  g_x   [N_NODES * EMBED];
__device__ __align__(1024) __half g_yTh [HID * N_NODES];             // (X@W)^T fp16, K-major B
__device__ __align__(1024) float  g_h1  [N_NODES * HID];

// ---------------------------------------------------------------------------
static __device__ __forceinline__ uint32_t smem_u32(const void* p) {
    uint32_t a;
    asm("{ .reg .u64 t; cvta.to.shared.u64 t, %1; cvt.u32.u64 %0, t; }" : "=r"(a) : "l"(p));
    return a;
}
#define SWZ(b) ((b) ^ (((b) >> 3) & 0x70))

static __device__ __forceinline__ void cp_async16(uint32_t dst, const void* src, uint32_t nbytes) {
    asm volatile("cp.async.cg.shared.global [%0], [%1], 16, %2;"
        :: "r"(dst), "l"(src), "r"(nbytes) : "memory");
}
#define CP_COMMIT() asm volatile("cp.async.commit_group;" ::: "memory")

static __device__ __forceinline__ void ldsm_x4(uint32_t r[4], uint32_t addr) {
    asm volatile("ldmatrix.sync.aligned.m8n8.x4.shared.b16 {%0,%1,%2,%3}, [%4];"
        : "=r"(r[0]), "=r"(r[1]), "=r"(r[2]), "=r"(r[3]) : "r"(addr));
}
static __device__ __forceinline__ void mma16816(float c[4], const uint32_t a[4],
                                                uint32_t b0, uint32_t b1) {
    asm volatile("mma.sync.aligned.m16n8k16.row.col.f32.f16.f16.f32 "
        "{%0,%1,%2,%3}, {%4,%5,%6,%7}, {%8,%9}, {%0,%1,%2,%3};"
        : "+f"(c[0]), "+f"(c[1]), "+f"(c[2]), "+f"(c[3])
        : "r"(a[0]), "r"(a[1]), "r"(a[2]), "r"(a[3]), "r"(b0), "r"(b1));
}

// ---------------------------------------------------------------------------
// Kernel 0: adj (fp32) -> g_adjh (fp16, scaled by 2^14)
// ---------------------------------------------------------------------------
__global__ void __launch_bounds__(256) convert_adj_kernel(const float* __restrict__ adj) {
    size_t i = ((size_t)blockIdx.x * 256 + threadIdx.x) * 8;
    if (i >= (size_t)N_NODES * N_NODES) return;
    float4 v0 = *(const float4*)(adj + i);
    float4 v1 = *(const float4*)(adj + i + 4);
    __half2 h[4];
    h[0] = __floats2half2_rn(v0.x * ADJ_SCALE, v0.y * ADJ_SCALE);
    h[1] = __floats2half2_rn(v0.z * ADJ_SCALE, v0.w * ADJ_SCALE);
    h[2] = __floats2half2_rn(v1.x * ADJ_SCALE, v1.y * ADJ_SCALE);
    h[3] = __floats2half2_rn(v1.z * ADJ_SCALE, v1.w * ADJ_SCALE);
    *(uint4*)(g_adjh + i) = *(uint4*)h;
}

// ---------------------------------------------------------------------------
// Kernel 1: gather + max over REP=8 embeddings
// ---------------------------------------------------------------------------
__global__ void gather_max_kernel(const int* __restrict__ nodes, const float* __restrict__ emb) {
    int m = blockIdx.x;
    __shared__ int idx[8];
    if (threadIdx.x < 8) idx[threadIdx.x] = nodes[(m + 1) * 8 + threadIdx.x];
    __syncthreads();
    for (int e = threadIdx.x; e < EMBED / 4; e += blockDim.x) {
        float4 mx = *(const float4*)(emb + (size_t)idx[0] * EMBED + e * 4);
        #pragma unroll
        for (int r = 1; r < 8; ++r) {
            float4 v = *(const float4*)(emb + (size_t)idx[r] * EMBED + e * 4);
            mx.x = fmaxf(mx.x, v.x); mx.y = fmaxf(mx.y, v.y);
            mx.z = fmaxf(mx.z, v.z); mx.w = fmaxf(mx.w, v.w);
        }
        *(float4*)(g_x + (size_t)m * EMBED + e * 4) = mx;
    }
}

// ---------------------------------------------------------------------------
// Kernel 2: small GEMM (exact fp32):  g_yTh[n][m] = fp16_rn( (X @ W)[m][n] )
// ---------------------------------------------------------------------------
__global__ void __launch_bounds__(256) small_gemm_kernel(const float* __restrict__ W, int K, int layer) {
    __shared__ float xs[32][17];
    __shared__ float ws[16][256];
    const float* X = layer ? g_h1 : g_x;
    int ldx = layer ? HID : EMBED;
    int m0 = blockIdx.x * 32;
    int tid = threadIdx.x;
    int tr = tid >> 6, tc = tid & 63;
    float acc[8][4] = {};

    for (int k0 = 0; k0 < K; k0 += 16) {
        #pragma unroll
        for (int j = 0; j < 2; ++j) {
            int idx = tid + j * 256; int r = idx >> 4, c = idx & 15;
            int gm = m0 + r, gk = k0 + c;
            xs[r][c] = (gm < N_NODES && gk < K) ? X[(size_t)gm * ldx + gk] : 0.0f;
        }
        #pragma unroll
        for (int j = 0; j < 4; ++j) {
            int idx = tid + j * 256; int r = idx >> 6, c4 = idx & 63;
            float4 v = make_float4(0.f, 0.f, 0.f, 0.f);
            if (k0 + r < K) v = *(const float4*)(W + (size_t)(k0 + r) * HID + c4 * 4);
            *(float4*)&ws[r][c4 * 4] = v;
        }
        __syncthreads();
        #pragma unroll
        for (int kk = 0; kk < 16; ++kk) {
            float4 w = *(const float4*)&ws[kk][tc * 4];
            #pragma unroll
            for (int i = 0; i < 8; ++i) {
                float xv = xs[tr * 8 + i][kk];
                acc[i][0] += xv * w.x; acc[i][1] += xv * w.y;
                acc[i][2] += xv * w.z; acc[i][3] += xv * w.w;
            }
        }
        __syncthreads();
    }
    #pragma unroll
    for (int i = 0; i < 8; ++i) {
        int m = m0 + tr * 8 + i;
        if (m < N_NODES) {
            #pragma unroll
            for (int j = 0; j < 4; ++j)
                g_yTh[(size_t)(tc * 4 + j) * N_NODES + m] = __float2half_rn(acc[i][j]);
        }
    }
}

// ---------------------------------------------------------------------------
// Kernel 3: big GEMM via mma.sync (fp16 in, fp32 accum)
// BM=80 x BN=256 per CTA, 125 CTAs. 8 warps: warp w owns cols [32w, 32w+32).
// Warp tile 80x32: 5 m16 x 4 n8 frags (20 MMAs / 7 ldsm per ks step).
// Register double-buffering over the 4 ks steps hides ldsm latency.
// ---------------------------------------------------------------------------
__global__ void __launch_bounds__(256, 1)
big_gemm_kernel(const float* __restrict__ bias, float* __restrict__ dout) {
    extern __shared__ char smem[];
    uint32_t sb = smem_u32(smem);
    int tid = threadIdx.x;
    int w = tid >> 5, lane = tid & 31;
    float* out = dout ? dout : g_h1;
    int m0 = blockIdx.x * BM;

    ((float*)(smem + SM_BIAS))[tid] = bias[tid];

    float acc[5][4][4];
    #pragma unroll
    for (int a = 0; a < 5; ++a)
        #pragma unroll
        for (int b = 0; b < 4; ++b)
            #pragma unroll
            for (int c = 0; c < 4; ++c) acc[a][b][c] = 0.f;

    // precomputed intra-stage ldsm byte offsets (ks=0); ks adds 32 bytes
    uint32_t a_off[5], b_off[2];
    #pragma unroll
    for (int mt = 0; mt < 5; ++mt)
        a_off[mt] = SWZ((uint32_t)(mt * 16 + (lane & 15)) * 128 + (lane >> 4) * 16);
    #pragma unroll
    for (int e = 0; e < 2; ++e) {
        uint32_t row = w * 32 + e * 16 + ((lane >> 4) & 1) * 8 + (lane & 7);
        b_off[e] = SWZ(row * 128 + ((lane >> 3) & 1) * 16);
    }
    // NOTE: SWZ only XORs bits[6:4] with bits[9:7]; ks*32 touches bits [5],[6]
    // which ARE swizzle-input bits, so recompute per ks instead of adding.

    auto fill = [&](int chunk) {
        int s = chunk & (STAGES - 1);
        int k0 = chunk * BK;
        uint32_t sa = sb + SM_A(s), sB = sb + SM_B(s);
        #pragma unroll
        for (int i = 0; i < 3; ++i) {             // A: 640 16B units
            int c = tid + i * 256;
            if (c < 640) {
                int row = c >> 3, ch = c & 7;
                int kk = k0 + ch * 8;
                int ok = kk < N_NODES;
                const __half* g = g_adjh + (size_t)(m0 + row) * N_NODES + (ok ? kk : 0);
                cp_async16(sa + SWZ(row * 128 + ch * 16), g, ok ? 16u : 0u);
            }
        }
        #pragma unroll
        for (int i = 0; i < 8; ++i) {             // B: 2048 16B units
            int c = tid + i * 256;
            int row = c >> 3, ch = c & 7;
            int kk = k0 + ch * 8;
            int ok = kk < N_NODES;
            const __half* g = g_yTh + (size_t)row * N_NODES + (ok ? kk : 0);
            cp_async16(sB + SWZ(row * 128 + ch * 16), g, ok ? 16u : 0u);
        }
        CP_COMMIT();
    };

    fill(0); fill(1); fill(2);

    uint32_t af[2][5][4], bf[2][2][4];

    for (int j = 0; j < NKCH; ++j) {
        asm volatile("cp.async.wait_group %0;" :: "n"(STAGES - 2));
        __syncthreads();
        // refill the stage consumed last iteration; overlaps with MMAs below
        if (j + 3 < NKCH) fill(j + 3); else CP_COMMIT();

        int s = j & (STAGES - 1);
        uint32_t sa = sb + SM_A(s), sB = sb + SM_B(s);

        // raw (unswizzled) base offsets per ks, swizzled at use
        // load ks=0 into buffer 0
        #pragma unroll
        for (int mt = 0; mt < 5; ++mt) {
            uint32_t off = (uint32_t)(mt * 16 + (lane & 15)) * 128 + (lane >> 4) * 16;
            ldsm_x4(af[0][mt], sa + SWZ(off));
        }
        #pragma unroll
        for (int e = 0; e < 2; ++e) {
            uint32_t row = w * 32 + e * 16 + ((lane >> 4) & 1) * 8 + (lane & 7);
            uint32_t off = row * 128 + ((lane >> 3) & 1) * 16;
            ldsm_x4(bf[0][e], sB + SWZ(off));
        }

        #pragma unroll
        for (int ks = 0; ks < 4; ++ks) {
            int cur = ks & 1, nxt = cur ^ 1;
            if (ks < 3) {   // prefetch ks+1 fragments before issuing MMAs
                #pragma unroll
                for (int mt = 0; mt < 5; ++mt) {
                    uint32_t off = (uint32_t)(mt * 16 + (lane & 15)) * 128
                                 + (ks + 1) * 32 + (lane >> 4) * 16;
                    ldsm_x4(af[nxt][mt], sa + SWZ(off));
                }
                #pragma unroll
                for (int e = 0; e < 2; ++e) {
                    uint32_t row = w * 32 + e * 16 + ((lane >> 4) & 1) * 8 + (lane & 7);
                    uint32_t off = row * 128 + (ks + 1) * 32 + ((lane >> 3) & 1) * 16;
                    ldsm_x4(bf[nxt][e], sB + SWZ(off));
                }
            }
            #pragma unroll
            for (int mt = 0; mt < 5; ++mt)
                #pragma unroll
                for (int nt = 0; nt < 4; ++nt)
                    mma16816(acc[mt][nt], af[cur][mt],
                             bf[cur][nt >> 1][(nt & 1) * 2], bf[cur][nt >> 1][(nt & 1) * 2 + 1]);
        }
    }

    // ---- epilogue: unscale, bias, leaky_relu, store fp32 ----
    const float* bsm = (const float*)(smem + SM_BIAS);
    int qr = lane >> 2, qc = lane & 3;
    #pragma unroll
    for (int mt = 0; mt < 5; ++mt) {
        int r0 = m0 + mt * 16 + qr;
        #pragma unroll
        for (int nt = 0; nt < 4; ++nt) {
            int col = w * 32 + nt * 8 + qc * 2;
            float b0 = bsm[col], b1 = bsm[col + 1];
            float v0 = acc[mt][nt][0] * ADJ_INV + b0;
            float v1 = acc[mt][nt][1] * ADJ_INV + b1;
            float v2 = acc[mt][nt][2] * ADJ_INV + b0;
            float v3 = acc[mt][nt][3] * ADJ_INV + b1;
            float2 p0 = make_float2(fmaxf(v0, 0.01f * v0), fmaxf(v1, 0.01f * v1));
            float2 p1 = make_float2(fmaxf(v2, 0.01f * v2), fmaxf(v3, 0.01f * v3));
            *(float2*)&out[(size_t)r0 * HID + col]       = p0;
            *(float2*)&out[(size_t)(r0 + 8) * HID + col] = p1;
        }
    }
}

// ---------------------------------------------------------------------------
extern "C" void kernel_launch(void* const* d_in, const int* in_sizes, int n_in,
                              void* d_out, int out_size) {
    (void)in_sizes; (void)n_in; (void)out_size;
    const int*   nodes = (const int*)  d_in[0];
    const float* emb   = (const float*)d_in[1];
    const float* adj   = (const float*)d_in[2];
    const float* W1    = (const float*)d_in[3];
    const float* b1    = (const float*)d_in[4];
    const float* W2    = (const float*)d_in[5];
    const float* b2    = (const float*)d_in[6];
    float* out = (float*)d_out;

    cudaFuncSetAttribute(big_gemm_kernel, cudaFuncAttributeMaxDynamicSharedMemorySize, SMEM_BYTES);

    size_t total = (size_t)N_NODES * N_NODES;
    int cgrid = (int)((total / 8 + 255) / 256);
    int gs = (N_NODES + 31) / 32;   // 313
    int gm = N_NODES / BM;          // 125, exact

    convert_adj_kernel<<<cgrid, 256>>>(adj);
    gather_max_kernel<<<N_NODES, 128>>>(nodes, emb);
    small_gemm_kernel<<<gs, 256>>>(W1, EMBED, 0);
    big_gemm_kernel<<<gm, 256, SMEM_BYTES>>>(b1, nullptr);
    small_gemm_kernel<<<gs, 256>>>(W2, HID, 1);
    big_gemm_kernel<<<gm, 256, SMEM_BYTES>>>(b2, out);
}

// round 7
// speedup vs baseline: 1.3443x; 1.2963x over previous
#include <cuda_runtime.h>
#include <cuda_fp16.h>
#include <cstdint>
#include <cstddef>

#define N_NODES 10000
#define EMBED   300
#define K0PAD   320       // EMBED padded to 5*64
#define HID     256

// ---- big GEMM tiling: BM=80 x BN=256, 125 CTAs, 1 CTA/SM ----
#define BM      80
#define BK      64
#define NKCH    157
#define STAGES  4

#define ADJ_SCALE  16384.0f
#define ADJ_INV    6.103515625e-05f

#define SM_BIAS   0
#define A_BYTES   (BM  * BK * 2)
#define B_BYTES   (256 * BK * 2)
#define STG_BYTES (A_BYTES + B_BYTES)
#define SM_A(s)   (1024 + (s) * STG_BYTES)
#define SM_B(s)   (SM_A(s) + A_BYTES)
#define SMEM_BYTES (1024 + STAGES * STG_BYTES)   // 173056

// ---- small GEMM tiling: 128m x 256n, K in {320,256} ----
#define SBM       128
#define SA_BYTES  (SBM * BK * 2)                 // 16384
#define SB_BYTES  (256 * BK * 2)                 // 32768
#define SSTG      (SA_BYTES + SB_BYTES)          // 49152
#define SSM_A(s)  ((s) * SSTG)
#define SSM_B(s)  (SSM_A(s) + SA_BYTES)
#define SSMEM_BYTES (3 * SSTG)                   // 147456

// ---- device scratch (only ever referenced from DEVICE code) ----
__device__ __align__(1024) __half g_adjh[(size_t)N_NODES * N_NODES]; // adj * 2^14
__device__ __align__(1024) __half g_xh  [N_NODES * K0PAD];           // gather result fp16, K-padded
__device__ __align__(1024) __half g_h1h [N_NODES * HID];             // layer-1 activations fp16
__device__ __align__(1024) __half g_yTh [HID * N_NODES];             // (X@W)^T fp16, K-major B
__device__ __align__(1024) __half g_w1t [HID * K0PAD];               // W1^T fp16 (zero K-pad)
__device__ __align__(1024) __half g_w2t [HID * HID];                 // W2^T fp16

// ---------------------------------------------------------------------------
static __device__ __forceinline__ uint32_t smem_u32(const void* p) {
    uint32_t a;
    asm("{ .reg .u64 t; cvta.to.shared.u64 t, %1; cvt.u32.u64 %0, t; }" : "=r"(a) : "l"(p));
    return a;
}
#define SWZ(b) ((b) ^ (((b) >> 3) & 0x70))

static __device__ __forceinline__ void cp_async16(uint32_t dst, const void* src, uint32_t nbytes) {
    asm volatile("cp.async.cg.shared.global [%0], [%1], 16, %2;"
        :: "r"(dst), "l"(src), "r"(nbytes) : "memory");
}
#define CP_COMMIT() asm volatile("cp.async.commit_group;" ::: "memory")

static __device__ __forceinline__ void ldsm_x4(uint32_t r[4], uint32_t addr) {
    asm volatile("ldmatrix.sync.aligned.m8n8.x4.shared.b16 {%0,%1,%2,%3}, [%4];"
        : "=r"(r[0]), "=r"(r[1]), "=r"(r[2]), "=r"(r[3]) : "r"(addr));
}
static __device__ __forceinline__ void mma16816(float c[4], const uint32_t a[4],
                                                uint32_t b0, uint32_t b1) {
    asm volatile("mma.sync.aligned.m16n8k16.row.col.f32.f16.f16.f32 "
        "{%0,%1,%2,%3}, {%4,%5,%6,%7}, {%8,%9}, {%0,%1,%2,%3};"
        : "+f"(c[0]), "+f"(c[1]), "+f"(c[2]), "+f"(c[3])
        : "r"(a[0]), "r"(a[1]), "r"(a[2]), "r"(a[3]), "r"(b0), "r"(b1));
}

// ---------------------------------------------------------------------------
// Kernel 0: adj (fp32) -> g_adjh (fp16, scaled by 2^14)
// ---------------------------------------------------------------------------
__global__ void __launch_bounds__(256) convert_adj_kernel(const float* __restrict__ adj) {
    size_t i = ((size_t)blockIdx.x * 256 + threadIdx.x) * 8;
    if (i >= (size_t)N_NODES * N_NODES) return;
    float4 v0 = *(const float4*)(adj + i);
    float4 v1 = *(const float4*)(adj + i + 4);
    __half2 h[4];
    h[0] = __floats2half2_rn(v0.x * ADJ_SCALE, v0.y * ADJ_SCALE);
    h[1] = __floats2half2_rn(v0.z * ADJ_SCALE, v0.w * ADJ_SCALE);
    h[2] = __floats2half2_rn(v1.x * ADJ_SCALE, v1.y * ADJ_SCALE);
    h[3] = __floats2half2_rn(v1.z * ADJ_SCALE, v1.w * ADJ_SCALE);
    *(uint4*)(g_adjh + i) = *(uint4*)h;
}

// ---------------------------------------------------------------------------
// Kernel 1: gather + max -> fp16 g_xh, K-padded to 320
// ---------------------------------------------------------------------------
__global__ void gather_max_kernel(const int* __restrict__ nodes, const float* __restrict__ emb) {
    int m = blockIdx.x;
    __shared__ int idx[8];
    if (threadIdx.x < 8) idx[threadIdx.x] = nodes[(m + 1) * 8 + threadIdx.x];
    __syncthreads();
    for (int e = threadIdx.x; e < K0PAD / 2; e += blockDim.x) {
        __half2 hv = __float2half2_rn(0.f);
        if (e < EMBED / 2) {
            float2 mx = *(const float2*)(emb + (size_t)idx[0] * EMBED + e * 2);
            #pragma unroll
            for (int r = 1; r < 8; ++r) {
                float2 v = *(const float2*)(emb + (size_t)idx[r] * EMBED + e * 2);
                mx.x = fmaxf(mx.x, v.x); mx.y = fmaxf(mx.y, v.y);
            }
            hv = __floats2half2_rn(mx.x, mx.y);
        }
        *(__half2*)(g_xh + (size_t)m * K0PAD + e * 2) = hv;
    }
}

// ---------------------------------------------------------------------------
// Kernel 2: weight transpose -> fp16, zero K-pad. which=0: W1 -> g_w1t[256][320]
//                                                which=1: W2 -> g_w2t[256][256]
// Destination selected in DEVICE code (never pass __device__ symbols from host).
// ---------------------------------------------------------------------------
__global__ void wtrans_kernel(const float* __restrict__ W, int K, int Kpad, int which) {
    __half* Wt = which ? g_w2t : g_w1t;
    int i = blockIdx.x * 256 + threadIdx.x;
    if (i >= 256 * Kpad) return;
    int n = i / Kpad, k = i % Kpad;
    Wt[i] = (k < K) ? __float2half_rn(W[(size_t)k * HID + n]) : __half(0);
}

// ---------------------------------------------------------------------------
// Kernel 3: small GEMM via mma:  g_yTh[n][m] = fp16( sum_k A[m][k] * Wt[n][k] )
// layer=0: A=g_xh (ldk=320, 5 kchunks), Wt=g_w1t
// layer=1: A=g_h1h (ldk=256, 4 kchunks), Wt=g_w2t
// 128m x 256n per CTA, 79 CTAs, 8 warps, warp tile 128x32, 3-stage cp.async,
// transposed epilogue staged through smem.
// ---------------------------------------------------------------------------
__global__ void __launch_bounds__(256, 1)
small_mma_kernel(int layer) {
    extern __shared__ char smem[];
    uint32_t sb = smem_u32(smem);
    const __half* A  = layer ? g_h1h : g_xh;
    const __half* Wt = layer ? g_w2t : g_w1t;
    const int ldk     = layer ? HID : K0PAD;
    const int kchunks = layer ? (HID / BK) : (K0PAD / BK);
    int tid = threadIdx.x;
    int w = tid >> 5, lane = tid & 31;
    int m0 = blockIdx.x * SBM;

    float acc[8][4][4];
    #pragma unroll
    for (int a = 0; a < 8; ++a)
        #pragma unroll
        for (int b = 0; b < 4; ++b)
            #pragma unroll
            for (int c = 0; c < 4; ++c) acc[a][b][c] = 0.f;

    auto fill = [&](int chunk) {
        int s = chunk % 3;
        int k0 = chunk * BK;
        uint32_t sa = sb + SSM_A(s), sB = sb + SSM_B(s);
        #pragma unroll
        for (int i = 0; i < 4; ++i) {             // A: 128 rows x 8 = 1024 units
            int c = tid + i * 256;
            int row = c >> 3, ch = c & 7;
            int gm = m0 + row;
            int ok = gm < N_NODES;
            const __half* g = A + (size_t)(ok ? gm : 0) * ldk + k0 + ch * 8;
            cp_async16(sa + SWZ(row * 128 + ch * 16), g, ok ? 16u : 0u);
        }
        #pragma unroll
        for (int i = 0; i < 8; ++i) {             // B: 256 rows x 8 = 2048 units
            int c = tid + i * 256;
            int row = c >> 3, ch = c & 7;
            cp_async16(sB + SWZ(row * 128 + ch * 16),
                       Wt + (size_t)row * ldk + k0 + ch * 8, 16u);
        }
        CP_COMMIT();
    };

    fill(0); fill(1);

    for (int j = 0; j < kchunks; ++j) {
        asm volatile("cp.async.wait_group %0;" :: "n"(1));
        __syncthreads();
        if (j + 2 < kchunks) fill(j + 2); else CP_COMMIT();

        int s = j % 3;
        uint32_t sa = sb + SSM_A(s), sB = sb + SSM_B(s);
        #pragma unroll
        for (int ks = 0; ks < 4; ++ks) {
            uint32_t bf[4], bf2[4];
            {
                uint32_t row = w * 32 + ((lane >> 4) & 1) * 8 + (lane & 7);
                uint32_t off = row * 128 + ks * 32 + ((lane >> 3) & 1) * 16;
                ldsm_x4(bf, sB + SWZ(off));
                uint32_t row2 = w * 32 + 16 + ((lane >> 4) & 1) * 8 + (lane & 7);
                uint32_t off2 = row2 * 128 + ks * 32 + ((lane >> 3) & 1) * 16;
                ldsm_x4(bf2, sB + SWZ(off2));
            }
            #pragma unroll
            for (int mt = 0; mt < 8; ++mt) {
                uint32_t af[4];
                uint32_t off = (uint32_t)(mt * 16 + (lane & 15)) * 128 + ks * 32 + (lane >> 4) * 16;
                ldsm_x4(af, sa + SWZ(off));
                mma16816(acc[mt][0], af, bf[0],  bf[1]);
                mma16816(acc[mt][1], af, bf[2],  bf[3]);
                mma16816(acc[mt][2], af, bf2[0], bf2[1]);
                mma16816(acc[mt][3], af, bf2[2], bf2[3]);
            }
        }
    }

    // ---- transposed epilogue: stage warp tile [32n][128m] in smem ----
    __syncthreads();
    __half* st = (__half*)(smem) + (size_t)w * 32 * 136;
    int qr = lane >> 2, qc = lane & 3;
    #pragma unroll
    for (int mt = 0; mt < 8; ++mt) {
        int ml = mt * 16 + qr;
        #pragma unroll
        for (int nt = 0; nt < 4; ++nt) {
            int nl = nt * 8 + qc * 2;
            st[(size_t)nl * 136 + ml]           = __float2half_rn(acc[mt][nt][0]);
            st[(size_t)(nl + 1) * 136 + ml]     = __float2half_rn(acc[mt][nt][1]);
            st[(size_t)nl * 136 + ml + 8]       = __float2half_rn(acc[mt][nt][2]);
            st[(size_t)(nl + 1) * 136 + ml + 8] = __float2half_rn(acc[mt][nt][3]);
        }
    }
    __syncwarp();
    #pragma unroll 4
    for (int nl = 0; nl < 32; ++nl) {
        int m = m0 + lane * 4;
        if (m < N_NODES)
            *(uint2*)&g_yTh[(size_t)(w * 32 + nl) * N_NODES + m] =
                *(uint2*)&st[(size_t)nl * 136 + lane * 4];
    }
}

// ---------------------------------------------------------------------------
// Kernel 4: big GEMM (R5 known-good mainloop; epilogue -> fp16 g_h1h or fp32 out)
// ---------------------------------------------------------------------------
__global__ void __launch_bounds__(256, 1)
big_gemm_kernel(const float* __restrict__ bias, float* __restrict__ dout) {
    extern __shared__ char smem[];
    uint32_t sb = smem_u32(smem);
    int tid = threadIdx.x;
    int w = tid >> 5, lane = tid & 31;
    int m0 = blockIdx.x * BM;

    ((float*)(smem + SM_BIAS))[tid] = bias[tid];

    float acc[5][4][4];
    #pragma unroll
    for (int a = 0; a < 5; ++a)
        #pragma unroll
        for (int b = 0; b < 4; ++b)
            #pragma unroll
            for (int c = 0; c < 4; ++c) acc[a][b][c] = 0.f;

    auto fill = [&](int chunk) {
        int s = chunk & (STAGES - 1);
        int k0 = chunk * BK;
        uint32_t sa = sb + SM_A(s), sB = sb + SM_B(s);
        #pragma unroll
        for (int i = 0; i < 3; ++i) {
            int c = tid + i * 256;
            if (c < 640) {
                int row = c >> 3, ch = c & 7;
                int kk = k0 + ch * 8;
                int ok = kk < N_NODES;
                const __half* g = g_adjh + (size_t)(m0 + row) * N_NODES + (ok ? kk : 0);
                cp_async16(sa + SWZ(row * 128 + ch * 16), g, ok ? 16u : 0u);
            }
        }
        #pragma unroll
        for (int i = 0; i < 8; ++i) {
            int c = tid + i * 256;
            int row = c >> 3, ch = c & 7;
            int kk = k0 + ch * 8;
            int ok = kk < N_NODES;
            const __half* g = g_yTh + (size_t)row * N_NODES + (ok ? kk : 0);
            cp_async16(sB + SWZ(row * 128 + ch * 16), g, ok ? 16u : 0u);
        }
        CP_COMMIT();
    };

    fill(0); fill(1); fill(2);

    for (int j = 0; j < NKCH; ++j) {
        asm volatile("cp.async.wait_group %0;" :: "n"(STAGES - 2));
        __syncthreads();
        if (j + 3 < NKCH) fill(j + 3); else CP_COMMIT();

        int s = j & (STAGES - 1);
        uint32_t sa = sb + SM_A(s), sB = sb + SM_B(s);
        #pragma unroll
        for (int ks = 0; ks < 4; ++ks) {
            uint32_t af[5][4];
            #pragma unroll
            for (int mt = 0; mt < 5; ++mt) {
                uint32_t off = (uint32_t)(mt * 16 + (lane & 15)) * 128 + ks * 32 + (lane >> 4) * 16;
                ldsm_x4(af[mt], sa + SWZ(off));
            }
            uint32_t bf[4], bf2[4];
            {
                uint32_t row = w * 32 + ((lane >> 4) & 1) * 8 + (lane & 7);
                uint32_t off = row * 128 + ks * 32 + ((lane >> 3) & 1) * 16;
                ldsm_x4(bf, sB + SWZ(off));
                uint32_t row2 = w * 32 + 16 + ((lane >> 4) & 1) * 8 + (lane & 7);
                uint32_t off2 = row2 * 128 + ks * 32 + ((lane >> 3) & 1) * 16;
                ldsm_x4(bf2, sB + SWZ(off2));
            }
            #pragma unroll
            for (int mt = 0; mt < 5; ++mt) {
                mma16816(acc[mt][0], af[mt], bf[0],  bf[1]);
                mma16816(acc[mt][1], af[mt], bf[2],  bf[3]);
                mma16816(acc[mt][2], af[mt], bf2[0], bf2[1]);
                mma16816(acc[mt][3], af[mt], bf2[2], bf2[3]);
            }
        }
    }

    const float* bsm = (const float*)(smem + SM_BIAS);
    int qr = lane >> 2, qc = lane & 3;
    #pragma unroll
    for (int mt = 0; mt < 5; ++mt) {
        int r0 = m0 + mt * 16 + qr;
        #pragma unroll
        for (int nt = 0; nt < 4; ++nt) {
            int col = w * 32 + nt * 8 + qc * 2;
            float b0 = bsm[col], b1 = bsm[col + 1];
            float v0 = acc[mt][nt][0] * ADJ_INV + b0;
            float v1 = acc[mt][nt][1] * ADJ_INV + b1;
            float v2 = acc[mt][nt][2] * ADJ_INV + b0;
            float v3 = acc[mt][nt][3] * ADJ_INV + b1;
            v0 = fmaxf(v0, 0.01f * v0); v1 = fmaxf(v1, 0.01f * v1);
            v2 = fmaxf(v2, 0.01f * v2); v3 = fmaxf(v3, 0.01f * v3);
            if (dout) {
                *(float2*)&dout[(size_t)r0 * HID + col]       = make_float2(v0, v1);
                *(float2*)&dout[(size_t)(r0 + 8) * HID + col] = make_float2(v2, v3);
            } else {
                *(__half2*)&g_h1h[(size_t)r0 * HID + col]       = __floats2half2_rn(v0, v1);
                *(__half2*)&g_h1h[(size_t)(r0 + 8) * HID + col] = __floats2half2_rn(v2, v3);
            }
        }
    }
}

// ---------------------------------------------------------------------------
extern "C" void kernel_launch(void* const* d_in, const int* in_sizes, int n_in,
                              void* d_out, int out_size) {
    (void)in_sizes; (void)n_in; (void)out_size;
    const int*   nodes = (const int*)  d_in[0];
    const float* emb   = (const float*)d_in[1];
    const float* adj   = (const float*)d_in[2];
    const float* W1    = (const float*)d_in[3];
    const float* b1    = (const float*)d_in[4];
    const float* W2    = (const float*)d_in[5];
    const float* b2    = (const float*)d_in[6];
    float* out = (float*)d_out;

    cudaFuncSetAttribute(big_gemm_kernel, cudaFuncAttributeMaxDynamicSharedMemorySize, SMEM_BYTES);
    cudaFuncSetAttribute(small_mma_kernel, cudaFuncAttributeMaxDynamicSharedMemorySize, SSMEM_BYTES);

    size_t total = (size_t)N_NODES * N_NODES;
    int cgrid = (int)((total / 8 + 255) / 256);
    int gm = N_NODES / BM;                     // 125
    int gsm = (N_NODES + SBM - 1) / SBM;       // 79

    convert_adj_kernel<<<cgrid, 256>>>(adj);
    gather_max_kernel<<<N_NODES, 128>>>(nodes, emb);
    wtrans_kernel<<<(256 * K0PAD + 255) / 256, 256>>>(W1, EMBED, K0PAD, 0);
    wtrans_kernel<<<(256 * HID + 255) / 256, 256>>>(W2, HID, HID, 1);

    small_mma_kernel<<<gsm, 256, SSMEM_BYTES>>>(0);          // g_yTh = (x@W1)^T
    big_gemm_kernel<<<gm, 256, SMEM_BYTES>>>(b1, nullptr);   // g_h1h = lrelu(adj@y1 + b1)
    small_mma_kernel<<<gsm, 256, SSMEM_BYTES>>>(1);          // g_yTh = (h1@W2)^T
    big_gemm_kernel<<<gm, 256, SMEM_BYTES>>>(b2, out);       // out   = lrelu(adj@y2 + b2)
}

// round 8
// speedup vs baseline: 1.5537x; 1.1558x over previous
#include <cuda_runtime.h>
#include <cuda_fp16.h>
#include <cstdint>
#include <cstddef>

#define N_NODES 10000
#define EMBED   300
#define K0PAD   320       // EMBED padded to 5*64
#define HID     256

// ---- big GEMM tiling: BM=80 x BN=256, 125 CTAs, 1 CTA/SM ----
#define BM      80
#define BK      64
#define NKCH    157
#define STAGES  4

#define ADJ_SCALE  16384.0f
#define ADJ_INV    6.103515625e-05f

#define SM_BIAS   0
#define A_BYTES   (BM  * BK * 2)
#define B_BYTES   (256 * BK * 2)
#define STG_BYTES (A_BYTES + B_BYTES)
#define SM_A(s)   (1024 + (s) * STG_BYTES)
#define SM_B(s)   (SM_A(s) + A_BYTES)
#define SMEM_BYTES (1024 + STAGES * STG_BYTES)   // 173056

// ---- small GEMM tiling: 128m x 256n, K in {320,256} ----
#define SBM       128
#define SA_BYTES  (SBM * BK * 2)
#define SB_BYTES  (256 * BK * 2)
#define SSTG      (SA_BYTES + SB_BYTES)
#define SSM_A(s)  ((s) * SSTG)
#define SSM_B(s)  (SSM_A(s) + SA_BYTES)
#define SSMEM_BYTES (3 * SSTG)                   // 147456

// ---- device scratch (only ever referenced from DEVICE code) ----
__device__ __align__(1024) __half g_adjh[(size_t)N_NODES * N_NODES]; // adj * 2^14 (written by layer-1 GEMM)
__device__ __align__(1024) __half g_xh  [N_NODES * K0PAD];
__device__ __align__(1024) __half g_h1h [N_NODES * HID];
__device__ __align__(1024) __half g_yTh [HID * N_NODES];
__device__ __align__(1024) __half g_w1t [HID * K0PAD];
__device__ __align__(1024) __half g_w2t [HID * HID];

// ---------------------------------------------------------------------------
static __device__ __forceinline__ uint32_t smem_u32(const void* p) {
    uint32_t a;
    asm("{ .reg .u64 t; cvta.to.shared.u64 t, %1; cvt.u32.u64 %0, t; }" : "=r"(a) : "l"(p));
    return a;
}
#define SWZ(b) ((b) ^ (((b) >> 3) & 0x70))

static __device__ __forceinline__ void cp_async16(uint32_t dst, const void* src, uint32_t nbytes) {
    asm volatile("cp.async.cg.shared.global [%0], [%1], 16, %2;"
        :: "r"(dst), "l"(src), "r"(nbytes) : "memory");
}
#define CP_COMMIT() asm volatile("cp.async.commit_group;" ::: "memory")

static __device__ __forceinline__ void ldsm_x4(uint32_t r[4], uint32_t addr) {
    asm volatile("ldmatrix.sync.aligned.m8n8.x4.shared.b16 {%0,%1,%2,%3}, [%4];"
        : "=r"(r[0]), "=r"(r[1]), "=r"(r[2]), "=r"(r[3]) : "r"(addr));
}
static __device__ __forceinline__ void mma16816(float c[4], const uint32_t a[4],
                                                uint32_t b0, uint32_t b1) {
    asm volatile("mma.sync.aligned.m16n8k16.row.col.f32.f16.f16.f32 "
        "{%0,%1,%2,%3}, {%4,%5,%6,%7}, {%8,%9}, {%0,%1,%2,%3};"
        : "+f"(c[0]), "+f"(c[1]), "+f"(c[2]), "+f"(c[3])
        : "r"(a[0]), "r"(a[1]), "r"(a[2]), "r"(a[3]), "r"(b0), "r"(b1));
}

// ---------------------------------------------------------------------------
// Kernel 1: gather + max -> fp16 g_xh, K-padded to 320
// ---------------------------------------------------------------------------
__global__ void gather_max_kernel(const int* __restrict__ nodes, const float* __restrict__ emb) {
    int m = blockIdx.x;
    __shared__ int idx[8];
    if (threadIdx.x < 8) idx[threadIdx.x] = nodes[(m + 1) * 8 + threadIdx.x];
    __syncthreads();
    for (int e = threadIdx.x; e < K0PAD / 2; e += blockDim.x) {
        __half2 hv = __float2half2_rn(0.f);
        if (e < EMBED / 2) {
            float2 mx = *(const float2*)(emb + (size_t)idx[0] * EMBED + e * 2);
            #pragma unroll
            for (int r = 1; r < 8; ++r) {
                float2 v = *(const float2*)(emb + (size_t)idx[r] * EMBED + e * 2);
                mx.x = fmaxf(mx.x, v.x); mx.y = fmaxf(mx.y, v.y);
            }
            hv = __floats2half2_rn(mx.x, mx.y);
        }
        *(__half2*)(g_xh + (size_t)m * K0PAD + e * 2) = hv;
    }
}

// ---------------------------------------------------------------------------
// Kernel 2: weight transpose -> fp16, zero K-pad (dest selected in device code)
// ---------------------------------------------------------------------------
__global__ void wtrans_kernel(const float* __restrict__ W, int K, int Kpad, int which) {
    __half* Wt = which ? g_w2t : g_w1t;
    int i = blockIdx.x * 256 + threadIdx.x;
    if (i >= 256 * Kpad) return;
    int n = i / Kpad, k = i % Kpad;
    Wt[i] = (k < K) ? __float2half_rn(W[(size_t)k * HID + n]) : __half(0);
}

// ---------------------------------------------------------------------------
// Kernel 3: small GEMM via mma:  g_yTh[n][m] = fp16( sum_k A[m][k] * Wt[n][k] )
// ---------------------------------------------------------------------------
__global__ void __launch_bounds__(256, 1)
small_mma_kernel(int layer) {
    extern __shared__ char smem[];
    uint32_t sb = smem_u32(smem);
    const __half* A  = layer ? g_h1h : g_xh;
    const __half* Wt = layer ? g_w2t : g_w1t;
    const int ldk     = layer ? HID : K0PAD;
    const int kchunks = layer ? (HID / BK) : (K0PAD / BK);
    int tid = threadIdx.x;
    int w = tid >> 5, lane = tid & 31;
    int m0 = blockIdx.x * SBM;

    float acc[8][4][4];
    #pragma unroll
    for (int a = 0; a < 8; ++a)
        #pragma unroll
        for (int b = 0; b < 4; ++b)
            #pragma unroll
            for (int c = 0; c < 4; ++c) acc[a][b][c] = 0.f;

    auto fill = [&](int chunk) {
        int s = chunk % 3;
        int k0 = chunk * BK;
        uint32_t sa = sb + SSM_A(s), sB = sb + SSM_B(s);
        #pragma unroll
        for (int i = 0; i < 4; ++i) {
            int c = tid + i * 256;
            int row = c >> 3, ch = c & 7;
            int gm = m0 + row;
            int ok = gm < N_NODES;
            const __half* g = A + (size_t)(ok ? gm : 0) * ldk + k0 + ch * 8;
            cp_async16(sa + SWZ(row * 128 + ch * 16), g, ok ? 16u : 0u);
        }
        #pragma unroll
        for (int i = 0; i < 8; ++i) {
            int c = tid + i * 256;
            int row = c >> 3, ch = c & 7;
            cp_async16(sB + SWZ(row * 128 + ch * 16),
                       Wt + (size_t)row * ldk + k0 + ch * 8, 16u);
        }
        CP_COMMIT();
    };

    fill(0); fill(1);

    for (int j = 0; j < kchunks; ++j) {
        asm volatile("cp.async.wait_group %0;" :: "n"(1));
        __syncthreads();
        if (j + 2 < kchunks) fill(j + 2); else CP_COMMIT();

        int s = j % 3;
        uint32_t sa = sb + SSM_A(s), sB = sb + SSM_B(s);
        #pragma unroll
        for (int ks = 0; ks < 4; ++ks) {
            uint32_t bf[4], bf2[4];
            {
                uint32_t row = w * 32 + ((lane >> 4) & 1) * 8 + (lane & 7);
                uint32_t off = row * 128 + ks * 32 + ((lane >> 3) & 1) * 16;
                ldsm_x4(bf, sB + SWZ(off));
                uint32_t row2 = w * 32 + 16 + ((lane >> 4) & 1) * 8 + (lane & 7);
                uint32_t off2 = row2 * 128 + ks * 32 + ((lane >> 3) & 1) * 16;
                ldsm_x4(bf2, sB + SWZ(off2));
            }
            #pragma unroll
            for (int mt = 0; mt < 8; ++mt) {
                uint32_t af[4];
                uint32_t off = (uint32_t)(mt * 16 + (lane & 15)) * 128 + ks * 32 + (lane >> 4) * 16;
                ldsm_x4(af, sa + SWZ(off));
                mma16816(acc[mt][0], af, bf[0],  bf[1]);
                mma16816(acc[mt][1], af, bf[2],  bf[3]);
                mma16816(acc[mt][2], af, bf2[0], bf2[1]);
                mma16816(acc[mt][3], af, bf2[2], bf2[3]);
            }
        }
    }

    __syncthreads();
    __half* st = (__half*)(smem) + (size_t)w * 32 * 136;
    int qr = lane >> 2, qc = lane & 3;
    #pragma unroll
    for (int mt = 0; mt < 8; ++mt) {
        int ml = mt * 16 + qr;
        #pragma unroll
        for (int nt = 0; nt < 4; ++nt) {
            int nl = nt * 8 + qc * 2;
            st[(size_t)nl * 136 + ml]           = __float2half_rn(acc[mt][nt][0]);
            st[(size_t)(nl + 1) * 136 + ml]     = __float2half_rn(acc[mt][nt][1]);
            st[(size_t)nl * 136 + ml + 8]       = __float2half_rn(acc[mt][nt][2]);
            st[(size_t)(nl + 1) * 136 + ml + 8] = __float2half_rn(acc[mt][nt][3]);
        }
    }
    __syncwarp();
    #pragma unroll 4
    for (int nl = 0; nl < 32; ++nl) {
        int m = m0 + lane * 4;
        if (m < N_NODES)
            *(uint2*)&g_yTh[(size_t)(w * 32 + nl) * N_NODES + m] =
                *(uint2*)&st[(size_t)nl * 136 + lane * 4];
    }
}

// ---------------------------------------------------------------------------
// Kernel 4: big GEMM. If adjf != nullptr (layer 1): A is read as fp32 from adjf,
// converted to scaled fp16 in registers, STS'd into the pipeline AND STG'd to
// g_adjh for layer 2 (fused conversion). Else (layer 2): A via cp.async from g_adjh.
// ---------------------------------------------------------------------------
__global__ void __launch_bounds__(256, 1)
big_gemm_kernel(const float* __restrict__ adjf, const float* __restrict__ bias,
                float* __restrict__ dout) {
    extern __shared__ char smem[];
    uint32_t sb = smem_u32(smem);
    int tid = threadIdx.x;
    int w = tid >> 5, lane = tid & 31;
    int m0 = blockIdx.x * BM;

    ((float*)(smem + SM_BIAS))[tid] = bias[tid];

    float acc[5][4][4];
    #pragma unroll
    for (int a = 0; a < 5; ++a)
        #pragma unroll
        for (int b = 0; b < 4; ++b)
            #pragma unroll
            for (int c = 0; c < 4; ++c) acc[a][b][c] = 0.f;

    // ---- A-convert pipeline state (layer 1): this thread owns 5 float4s ----
    // idx = tid + i*256 -> row = idx/16, c4 = idx%16, cols [c4*4, c4*4+4)
    float4 areg[5];
    int arow[5], acol[5];
    #pragma unroll
    for (int i = 0; i < 5; ++i) {
        int c = tid + i * 256;
        arow[i] = c >> 4;
        acol[i] = (c & 15) * 4;
    }

    auto ldgA = [&](int chunk) {          // layer-1: LDG fp32 A chunk into regs
        int k0 = chunk * BK;
        #pragma unroll
        for (int i = 0; i < 5; ++i) {
            int kk = k0 + acol[i];
            if (kk < N_NODES)
                areg[i] = *(const float4*)(adjf + (size_t)(m0 + arow[i]) * N_NODES + kk);
            else
                areg[i] = make_float4(0.f, 0.f, 0.f, 0.f);
        }
    };
    auto stsA = [&](int chunk) {          // layer-1: convert + STS + STG
        int s = chunk & (STAGES - 1);
        int k0 = chunk * BK;
        uint32_t sa = sb + SM_A(s);
        #pragma unroll
        for (int i = 0; i < 5; ++i) {
            __half2 h0 = __floats2half2_rn(areg[i].x * ADJ_SCALE, areg[i].y * ADJ_SCALE);
            __half2 h1 = __floats2half2_rn(areg[i].z * ADJ_SCALE, areg[i].w * ADJ_SCALE);
            uint2 pk = make_uint2(*(uint32_t*)&h0, *(uint32_t*)&h1);
            *(uint2*)(smem + (SWZ((uint32_t)arow[i] * 128 + acol[i] * 2) + SM_A(s))) = pk;
            int kk = k0 + acol[i];
            if (kk < N_NODES)
                *(uint2*)&g_adjh[(size_t)(m0 + arow[i]) * N_NODES + kk] = pk;
        }
        (void)sa;
    };
    auto fillA_async = [&](int chunk) {   // layer-2: cp.async fp16 A
        int s = chunk & (STAGES - 1);
        int k0 = chunk * BK;
        uint32_t sa = sb + SM_A(s);
        #pragma unroll
        for (int i = 0; i < 3; ++i) {
            int c = tid + i * 256;
            if (c < 640) {
                int row = c >> 3, ch = c & 7;
                int kk = k0 + ch * 8;
                int ok = kk < N_NODES;
                const __half* g = g_adjh + (size_t)(m0 + row) * N_NODES + (ok ? kk : 0);
                cp_async16(sa + SWZ(row * 128 + ch * 16), g, ok ? 16u : 0u);
            }
        }
    };
    auto fillB = [&](int chunk) {
        int s = chunk & (STAGES - 1);
        int k0 = chunk * BK;
        uint32_t sB = sb + SM_B(s);
        #pragma unroll
        for (int i = 0; i < 8; ++i) {
            int c = tid + i * 256;
            int row = c >> 3, ch = c & 7;
            int kk = k0 + ch * 8;
            int ok = kk < N_NODES;
            const __half* g = g_yTh + (size_t)row * N_NODES + (ok ? kk : 0);
            cp_async16(sB + SWZ(row * 128 + ch * 16), g, ok ? 16u : 0u);
        }
    };

    // ---- prologue ----
    if (adjf) {
        ldgA(0); stsA(0); ldgA(1); stsA(1); ldgA(2); stsA(2); ldgA(3);
        fillB(0); CP_COMMIT(); fillB(1); CP_COMMIT(); fillB(2); CP_COMMIT();
    } else {
        fillA_async(0); fillB(0); CP_COMMIT();
        fillA_async(1); fillB(1); CP_COMMIT();
        fillA_async(2); fillB(2); CP_COMMIT();
    }

    for (int j = 0; j < NKCH; ++j) {
        asm volatile("cp.async.wait_group %0;" :: "n"(STAGES - 2));
        __syncthreads();
        if (adjf) {
            if (j + 3 < NKCH) {
                fillB(j + 3);
                stsA(j + 3);                     // regs loaded last iteration
                if (j + 4 < NKCH) ldgA(j + 4);   // prefetch next chunk's fp32 A
            }
            CP_COMMIT();
        } else {
            if (j + 3 < NKCH) { fillA_async(j + 3); fillB(j + 3); }
            CP_COMMIT();
        }

        int s = j & (STAGES - 1);
        uint32_t sa = sb + SM_A(s), sB = sb + SM_B(s);
        #pragma unroll
        for (int ks = 0; ks < 4; ++ks) {
            uint32_t af[5][4];
            #pragma unroll
            for (int mt = 0; mt < 5; ++mt) {
                uint32_t off = (uint32_t)(mt * 16 + (lane & 15)) * 128 + ks * 32 + (lane >> 4) * 16;
                ldsm_x4(af[mt], sa + SWZ(off));
            }
            uint32_t bf[4], bf2[4];
            {
                uint32_t row = w * 32 + ((lane >> 4) & 1) * 8 + (lane & 7);
                uint32_t off = row * 128 + ks * 32 + ((lane >> 3) & 1) * 16;
                ldsm_x4(bf, sB + SWZ(off));
                uint32_t row2 = w * 32 + 16 + ((lane >> 4) & 1) * 8 + (lane & 7);
                uint32_t off2 = row2 * 128 + ks * 32 + ((lane >> 3) & 1) * 16;
                ldsm_x4(bf2, sB + SWZ(off2));
            }
            #pragma unroll
            for (int mt = 0; mt < 5; ++mt) {
                mma16816(acc[mt][0], af[mt], bf[0],  bf[1]);
                mma16816(acc[mt][1], af[mt], bf[2],  bf[3]);
                mma16816(acc[mt][2], af[mt], bf2[0], bf2[1]);
                mma16816(acc[mt][3], af[mt], bf2[2], bf2[3]);
            }
        }
    }

    const float* bsm = (const float*)(smem + SM_BIAS);
    int qr = lane >> 2, qc = lane & 3;
    #pragma unroll
    for (int mt = 0; mt < 5; ++mt) {
        int r0 = m0 + mt * 16 + qr;
        #pragma unroll
        for (int nt = 0; nt < 4; ++nt) {
            int col = w * 32 + nt * 8 + qc * 2;
            float b0 = bsm[col], b1 = bsm[col + 1];
            float v0 = acc[mt][nt][0] * ADJ_INV + b0;
            float v1 = acc[mt][nt][1] * ADJ_INV + b1;
            float v2 = acc[mt][nt][2] * ADJ_INV + b0;
            float v3 = acc[mt][nt][3] * ADJ_INV + b1;
            v0 = fmaxf(v0, 0.01f * v0); v1 = fmaxf(v1, 0.01f * v1);
            v2 = fmaxf(v2, 0.01f * v2); v3 = fmaxf(v3, 0.01f * v3);
            if (dout) {
                *(float2*)&dout[(size_t)r0 * HID + col]       = make_float2(v0, v1);
                *(float2*)&dout[(size_t)(r0 + 8) * HID + col] = make_float2(v2, v3);
            } else {
                *(__half2*)&g_h1h[(size_t)r0 * HID + col]       = __floats2half2_rn(v0, v1);
                *(__half2*)&g_h1h[(size_t)(r0 + 8) * HID + col] = __floats2half2_rn(v2, v3);
            }
        }
    }
}

// ---------------------------------------------------------------------------
extern "C" void kernel_launch(void* const* d_in, const int* in_sizes, int n_in,
                              void* d_out, int out_size) {
    (void)in_sizes; (void)n_in; (void)out_size;
    const int*   nodes = (const int*)  d_in[0];
    const float* emb   = (const float*)d_in[1];
    const float* adj   = (const float*)d_in[2];
    const float* W1    = (const float*)d_in[3];
    const float* b1    = (const float*)d_in[4];
    const float* W2    = (const float*)d_in[5];
    const float* b2    = (const float*)d_in[6];
    float* out = (float*)d_out;

    cudaFuncSetAttribute(big_gemm_kernel, cudaFuncAttributeMaxDynamicSharedMemorySize, SMEM_BYTES);
    cudaFuncSetAttribute(small_mma_kernel, cudaFuncAttributeMaxDynamicSharedMemorySize, SSMEM_BYTES);

    int gm = N_NODES / BM;                     // 125
    int gsm = (N_NODES + SBM - 1) / SBM;       // 79

    gather_max_kernel<<<N_NODES, 128>>>(nodes, emb);
    wtrans_kernel<<<(256 * K0PAD + 255) / 256, 256>>>(W1, EMBED, K0PAD, 0);
    wtrans_kernel<<<(256 * HID + 255) / 256, 256>>>(W2, HID, HID, 1);

    small_mma_kernel<<<gsm, 256, SSMEM_BYTES>>>(0);               // g_yTh = (x@W1)^T
    big_gemm_kernel<<<gm, 256, SMEM_BYTES>>>(adj, b1, nullptr);   // fused convert; -> g_h1h, g_adjh
    small_mma_kernel<<<gsm, 256, SSMEM_BYTES>>>(1);               // g_yTh = (h1@W2)^T
    big_gemm_kernel<<<gm, 256, SMEM_BYTES>>>(nullptr, b2, out);   // -> fp32 out
}

// round 9
// speedup vs baseline: 1.5704x; 1.0107x over previous
#include <cuda_runtime.h>
#include <cuda_fp16.h>
#include <cstdint>
#include <cstddef>

#define N_NODES 10000
#define EMBED   300
#define K0PAD   320       // EMBED padded to 5*64
#define HID     256

// ---- big GEMM tiling: BM=80 x BN=256, 125 CTAs, 1 CTA/SM ----
#define BM      80
#define BK      64
#define NKCH    157
#define STAGES  4

#define ADJ_SCALE  16384.0f
#define ADJ_INV    6.103515625e-05f

#define SM_BIAS   0
#define A_BYTES   (BM  * BK * 2)
#define B_BYTES   (256 * BK * 2)
#define STG_BYTES (A_BYTES + B_BYTES)
#define SM_A(s)   (1024 + (s) * STG_BYTES)
#define SM_B(s)   (SM_A(s) + A_BYTES)
#define SMEM_BYTES (1024 + STAGES * STG_BYTES)   // 173056

// ---- small GEMM tiling: 128m x 256n ----
#define SBM       128
#define SA_BYTES  (SBM * BK * 2)
#define SB_BYTES  (256 * BK * 2)
#define SSTG      (SA_BYTES + SB_BYTES)
#define SSM_A(s)  ((s) * SSTG)
#define SSM_B(s)  (SSM_A(s) + SA_BYTES)
#define SSMEM_BYTES (3 * SSTG)                   // 147456

// ---- device scratch (only ever referenced from DEVICE code) ----
__device__ __align__(1024) __half g_adjh[(size_t)N_NODES * N_NODES];
__device__ __align__(1024) __half g_xh  [N_NODES * K0PAD];
__device__ __align__(1024) __half g_h1h [N_NODES * HID];
__device__ __align__(1024) __half g_yTh [HID * N_NODES];
__device__ __align__(1024) __half g_w1t [HID * K0PAD];
__device__ __align__(1024) __half g_w2t [HID * HID];

// ---------------------------------------------------------------------------
static __device__ __forceinline__ uint32_t smem_u32(const void* p) {
    uint32_t a;
    asm("{ .reg .u64 t; cvta.to.shared.u64 t, %1; cvt.u32.u64 %0, t; }" : "=r"(a) : "l"(p));
    return a;
}
#define SWZ(b) ((b) ^ (((b) >> 3) & 0x70))

static __device__ __forceinline__ void cp_async16(uint32_t dst, const void* src, uint32_t nbytes) {
    asm volatile("cp.async.cg.shared.global [%0], [%1], 16, %2;"
        :: "r"(dst), "l"(src), "r"(nbytes) : "memory");
}
#define CP_COMMIT() asm volatile("cp.async.commit_group;" ::: "memory")

static __device__ __forceinline__ void ldsm_x4(uint32_t r[4], uint32_t addr) {
    asm volatile("ldmatrix.sync.aligned.m8n8.x4.shared.b16 {%0,%1,%2,%3}, [%4];"
        : "=r"(r[0]), "=r"(r[1]), "=r"(r[2]), "=r"(r[3]) : "r"(addr));
}
static __device__ __forceinline__ void mma16816(float c[4], const uint32_t a[4],
                                                uint32_t b0, uint32_t b1) {
    asm volatile("mma.sync.aligned.m16n8k16.row.col.f32.f16.f16.f32 "
        "{%0,%1,%2,%3}, {%4,%5,%6,%7}, {%8,%9}, {%0,%1,%2,%3};"
        : "+f"(c[0]), "+f"(c[1]), "+f"(c[2]), "+f"(c[3])
        : "r"(a[0]), "r"(a[1]), "r"(a[2]), "r"(a[3]), "r"(b0), "r"(b1));
}

// ---------------------------------------------------------------------------
// Kernel 1 (fused prep): blocks [0,10000): gather+max -> g_xh
//                        blocks [10000,10640): W1^T -> g_w1t
//                        blocks [10640,11152): W2^T -> g_w2t
// ---------------------------------------------------------------------------
#define GB_GATHER 10000
#define GB_W1     (GB_GATHER + (256 * K0PAD) / 128)   // 10000 + 640
#define GB_END    (GB_W1 + (256 * HID) / 128)         // + 512

__global__ void prep_kernel(const int* __restrict__ nodes, const float* __restrict__ emb,
                            const float* __restrict__ W1, const float* __restrict__ W2) {
    int b = blockIdx.x;
    if (b < GB_GATHER) {
        int m = b;
        __shared__ int idx[8];
        if (threadIdx.x < 8) idx[threadIdx.x] = nodes[(m + 1) * 8 + threadIdx.x];
        __syncthreads();
        for (int e = threadIdx.x; e < K0PAD / 2; e += blockDim.x) {
            __half2 hv = __float2half2_rn(0.f);
            if (e < EMBED / 2) {
                float2 mx = *(const float2*)(emb + (size_t)idx[0] * EMBED + e * 2);
                #pragma unroll
                for (int r = 1; r < 8; ++r) {
                    float2 v = *(const float2*)(emb + (size_t)idx[r] * EMBED + e * 2);
                    mx.x = fmaxf(mx.x, v.x); mx.y = fmaxf(mx.y, v.y);
                }
                hv = __floats2half2_rn(mx.x, mx.y);
            }
            *(__half2*)(g_xh + (size_t)m * K0PAD + e * 2) = hv;
        }
    } else if (b < GB_W1) {
        int i = (b - GB_GATHER) * 128 + threadIdx.x;   // [0, 256*320)
        int n = i / K0PAD, k = i % K0PAD;
        g_w1t[i] = (k < EMBED) ? __float2half_rn(W1[(size_t)k * HID + n]) : __half(0);
    } else {
        int i = (b - GB_W1) * 128 + threadIdx.x;       // [0, 256*256)
        int n = i / HID, k = i % HID;
        g_w2t[i] = __float2half_rn(W2[(size_t)k * HID + n]);
    }
}

// ---------------------------------------------------------------------------
// Kernel 3: small GEMM via mma:  g_yTh[n][m] = fp16( sum_k A[m][k] * Wt[n][k] )
// ---------------------------------------------------------------------------
__global__ void __launch_bounds__(256, 1)
small_mma_kernel(int layer) {
    extern __shared__ char smem[];
    uint32_t sb = smem_u32(smem);
    const __half* A  = layer ? g_h1h : g_xh;
    const __half* Wt = layer ? g_w2t : g_w1t;
    const int ldk     = layer ? HID : K0PAD;
    const int kchunks = layer ? (HID / BK) : (K0PAD / BK);
    int tid = threadIdx.x;
    int w = tid >> 5, lane = tid & 31;
    int m0 = blockIdx.x * SBM;
    const int ksshift = ((w >> 2) & 1) * 2;   // SMSP co-resident warps (w, w+4) anti-phased

    float acc[8][4][4];
    #pragma unroll
    for (int a = 0; a < 8; ++a)
        #pragma unroll
        for (int b = 0; b < 4; ++b)
            #pragma unroll
            for (int c = 0; c < 4; ++c) acc[a][b][c] = 0.f;

    auto fill = [&](int chunk) {
        int s = chunk % 3;
        int k0 = chunk * BK;
        uint32_t sa = sb + SSM_A(s), sB = sb + SSM_B(s);
        #pragma unroll
        for (int i = 0; i < 4; ++i) {
            int c = tid + i * 256;
            int row = c >> 3, ch = c & 7;
            int gm = m0 + row;
            int ok = gm < N_NODES;
            const __half* g = A + (size_t)(ok ? gm : 0) * ldk + k0 + ch * 8;
            cp_async16(sa + SWZ(row * 128 + ch * 16), g, ok ? 16u : 0u);
        }
        #pragma unroll
        for (int i = 0; i < 8; ++i) {
            int c = tid + i * 256;
            int row = c >> 3, ch = c & 7;
            cp_async16(sB + SWZ(row * 128 + ch * 16),
                       Wt + (size_t)row * ldk + k0 + ch * 8, 16u);
        }
        CP_COMMIT();
    };

    fill(0); fill(1);

    for (int j = 0; j < kchunks; ++j) {
        asm volatile("cp.async.wait_group %0;" :: "n"(1));
        __syncthreads();
        if (j + 2 < kchunks) fill(j + 2); else CP_COMMIT();

        int s = j % 3;
        uint32_t sa = sb + SSM_A(s), sB = sb + SSM_B(s);
        #pragma unroll
        for (int ks = 0; ks < 4; ++ks) {
            int kse = (ks + ksshift) & 3;
            uint32_t bf[4], bf2[4];
            {
                uint32_t row = w * 32 + ((lane >> 4) & 1) * 8 + (lane & 7);
                uint32_t off = row * 128 + kse * 32 + ((lane >> 3) & 1) * 16;
                ldsm_x4(bf, sB + SWZ(off));
                uint32_t row2 = w * 32 + 16 + ((lane >> 4) & 1) * 8 + (lane & 7);
                uint32_t off2 = row2 * 128 + kse * 32 + ((lane >> 3) & 1) * 16;
                ldsm_x4(bf2, sB + SWZ(off2));
            }
            #pragma unroll
            for (int mt = 0; mt < 8; ++mt) {
                uint32_t af[4];
                uint32_t off = (uint32_t)(mt * 16 + (lane & 15)) * 128 + kse * 32 + (lane >> 4) * 16;
                ldsm_x4(af, sa + SWZ(off));
                mma16816(acc[mt][0], af, bf[0],  bf[1]);
                mma16816(acc[mt][1], af, bf[2],  bf[3]);
                mma16816(acc[mt][2], af, bf2[0], bf2[1]);
                mma16816(acc[mt][3], af, bf2[2], bf2[3]);
            }
        }
    }

    __syncthreads();
    __half* st = (__half*)(smem) + (size_t)w * 32 * 136;
    int qr = lane >> 2, qc = lane & 3;
    #pragma unroll
    for (int mt = 0; mt < 8; ++mt) {
        int ml = mt * 16 + qr;
        #pragma unroll
        for (int nt = 0; nt < 4; ++nt) {
            int nl = nt * 8 + qc * 2;
            st[(size_t)nl * 136 + ml]           = __float2half_rn(acc[mt][nt][0]);
            st[(size_t)(nl + 1) * 136 + ml]     = __float2half_rn(acc[mt][nt][1]);
            st[(size_t)nl * 136 + ml + 8]       = __float2half_rn(acc[mt][nt][2]);
            st[(size_t)(nl + 1) * 136 + ml + 8] = __float2half_rn(acc[mt][nt][3]);
        }
    }
    __syncwarp();
    #pragma unroll 4
    for (int nl = 0; nl < 32; ++nl) {
        int m = m0 + lane * 4;
        if (m < N_NODES)
            *(uint2*)&g_yTh[(size_t)(w * 32 + nl) * N_NODES + m] =
                *(uint2*)&st[(size_t)nl * 136 + lane * 4];
    }
}

// ---------------------------------------------------------------------------
// Kernel 4: big GEMM. Layer 1 (adjf != null): fused fp32->fp16 A conversion
// (LDG + STS + STG to g_adjh). Layer 2: cp.async from g_adjh.
// SMSP warp pairs are ks-anti-phased to overlap LDSM bursts with MMA bursts.
// ---------------------------------------------------------------------------
__global__ void __launch_bounds__(256, 1)
big_gemm_kernel(const float* __restrict__ adjf, const float* __restrict__ bias,
                float* __restrict__ dout) {
    extern __shared__ char smem[];
    uint32_t sb = smem_u32(smem);
    int tid = threadIdx.x;
    int w = tid >> 5, lane = tid & 31;
    int m0 = blockIdx.x * BM;
    const int ksshift = ((w >> 2) & 1) * 2;   // warps w and w+4 share an SMSP

    ((float*)(smem + SM_BIAS))[tid] = bias[tid];

    float acc[5][4][4];
    #pragma unroll
    for (int a = 0; a < 5; ++a)
        #pragma unroll
        for (int b = 0; b < 4; ++b)
            #pragma unroll
            for (int c = 0; c < 4; ++c) acc[a][b][c] = 0.f;

    float4 areg[5];
    int arow[5], acol[5];
    #pragma unroll
    for (int i = 0; i < 5; ++i) {
        int c = tid + i * 256;
        arow[i] = c >> 4;
        acol[i] = (c & 15) * 4;
    }

    auto ldgA = [&](int chunk) {
        int k0 = chunk * BK;
        #pragma unroll
        for (int i = 0; i < 5; ++i) {
            int kk = k0 + acol[i];
            if (kk < N_NODES)
                areg[i] = *(const float4*)(adjf + (size_t)(m0 + arow[i]) * N_NODES + kk);
            else
                areg[i] = make_float4(0.f, 0.f, 0.f, 0.f);
        }
    };
    auto stsA = [&](int chunk) {
        int s = chunk & (STAGES - 1);
        int k0 = chunk * BK;
        #pragma unroll
        for (int i = 0; i < 5; ++i) {
            __half2 h0 = __floats2half2_rn(areg[i].x * ADJ_SCALE, areg[i].y * ADJ_SCALE);
            __half2 h1 = __floats2half2_rn(areg[i].z * ADJ_SCALE, areg[i].w * ADJ_SCALE);
            uint2 pk = make_uint2(*(uint32_t*)&h0, *(uint32_t*)&h1);
            *(uint2*)(smem + (SWZ((uint32_t)arow[i] * 128 + acol[i] * 2) + SM_A(s))) = pk;
            int kk = k0 + acol[i];
            if (kk < N_NODES)
                *(uint2*)&g_adjh[(size_t)(m0 + arow[i]) * N_NODES + kk] = pk;
        }
    };
    auto fillA_async = [&](int chunk) {
        int s = chunk & (STAGES - 1);
        int k0 = chunk * BK;
        uint32_t sa = sb + SM_A(s);
        #pragma unroll
        for (int i = 0; i < 3; ++i) {
            int c = tid + i * 256;
            if (c < 640) {
                int row = c >> 3, ch = c & 7;
                int kk = k0 + ch * 8;
                int ok = kk < N_NODES;
                const __half* g = g_adjh + (size_t)(m0 + row) * N_NODES + (ok ? kk : 0);
                cp_async16(sa + SWZ(row * 128 + ch * 16), g, ok ? 16u : 0u);
            }
        }
    };
    auto fillB = [&](int chunk) {
        int s = chunk & (STAGES - 1);
        int k0 = chunk * BK;
        uint32_t sB = sb + SM_B(s);
        #pragma unroll
        for (int i = 0; i < 8; ++i) {
            int c = tid + i * 256;
            int row = c >> 3, ch = c & 7;
            int kk = k0 + ch * 8;
            int ok = kk < N_NODES;
            const __half* g = g_yTh + (size_t)row * N_NODES + (ok ? kk : 0);
            cp_async16(sB + SWZ(row * 128 + ch * 16), g, ok ? 16u : 0u);
        }
    };

    if (adjf) {
        ldgA(0); stsA(0); ldgA(1); stsA(1); ldgA(2); stsA(2); ldgA(3);
        fillB(0); CP_COMMIT(); fillB(1); CP_COMMIT(); fillB(2); CP_COMMIT();
    } else {
        fillA_async(0); fillB(0); CP_COMMIT();
        fillA_async(1); fillB(1); CP_COMMIT();
        fillA_async(2); fillB(2); CP_COMMIT();
    }

    for (int j = 0; j < NKCH; ++j) {
        asm volatile("cp.async.wait_group %0;" :: "n"(STAGES - 2));
        __syncthreads();
        if (adjf) {
            if (j + 3 < NKCH) {
                fillB(j + 3);
                stsA(j + 3);
                if (j + 4 < NKCH) ldgA(j + 4);
            }
            CP_COMMIT();
        } else {
            if (j + 3 < NKCH) { fillA_async(j + 3); fillB(j + 3); }
            CP_COMMIT();
        }

        int s = j & (STAGES - 1);
        uint32_t sa = sb + SM_A(s), sB = sb + SM_B(s);
        #pragma unroll
        for (int ks = 0; ks < 4; ++ks) {
            int kse = (ks + ksshift) & 3;
            uint32_t af[5][4];
            #pragma unroll
            for (int mt = 0; mt < 5; ++mt) {
                uint32_t off = (uint32_t)(mt * 16 + (lane & 15)) * 128 + kse * 32 + (lane >> 4) * 16;
                ldsm_x4(af[mt], sa + SWZ(off));
            }
            uint32_t bf[4], bf2[4];
            {
                uint32_t row = w * 32 + ((lane >> 4) & 1) * 8 + (lane & 7);
                uint32_t off = row * 128 + kse * 32 + ((lane >> 3) & 1) * 16;
                ldsm_x4(bf, sB + SWZ(off));
                uint32_t row2 = w * 32 + 16 + ((lane >> 4) & 1) * 8 + (lane & 7);
                uint32_t off2 = row2 * 128 + kse * 32 + ((lane >> 3) & 1) * 16;
                ldsm_x4(bf2, sB + SWZ(off2));
            }
            #pragma unroll
            for (int mt = 0; mt < 5; ++mt) {
                mma16816(acc[mt][0], af[mt], bf[0],  bf[1]);
                mma16816(acc[mt][1], af[mt], bf[2],  bf[3]);
                mma16816(acc[mt][2], af[mt], bf2[0], bf2[1]);
                mma16816(acc[mt][3], af[mt], bf2[2], bf2[3]);
            }
        }
    }

    const float* bsm = (const float*)(smem + SM_BIAS);
    int qr = lane >> 2, qc = lane & 3;
    #pragma unroll
    for (int mt = 0; mt < 5; ++mt) {
        int r0 = m0 + mt * 16 + qr;
        #pragma unroll
        for (int nt = 0; nt < 4; ++nt) {
            int col = w * 32 + nt * 8 + qc * 2;
            float b0 = bsm[col], b1 = bsm[col + 1];
            float v0 = acc[mt][nt][0] * ADJ_INV + b0;
            float v1 = acc[mt][nt][1] * ADJ_INV + b1;
            float v2 = acc[mt][nt][2] * ADJ_INV + b0;
            float v3 = acc[mt][nt][3] * ADJ_INV + b1;
            v0 = fmaxf(v0, 0.01f * v0); v1 = fmaxf(v1, 0.01f * v1);
            v2 = fmaxf(v2, 0.01f * v2); v3 = fmaxf(v3, 0.01f * v3);
            if (dout) {
                *(float2*)&dout[(size_t)r0 * HID + col]       = make_float2(v0, v1);
                *(float2*)&dout[(size_t)(r0 + 8) * HID + col] = make_float2(v2, v3);
            } else {
                *(__half2*)&g_h1h[(size_t)r0 * HID + col]       = __floats2half2_rn(v0, v1);
                *(__half2*)&g_h1h[(size_t)(r0 + 8) * HID + col] = __floats2half2_rn(v2, v3);
            }
        }
    }
}

// ---------------------------------------------------------------------------
extern "C" void kernel_launch(void* const* d_in, const int* in_sizes, int n_in,
                              void* d_out, int out_size) {
    (void)in_sizes; (void)n_in; (void)out_size;
    const int*   nodes = (const int*)  d_in[0];
    const float* emb   = (const float*)d_in[1];
    const float* adj   = (const float*)d_in[2];
    const float* W1    = (const float*)d_in[3];
    const float* b1    = (const float*)d_in[4];
    const float* W2    = (const float*)d_in[5];
    const float* b2    = (const float*)d_in[6];
    float* out = (float*)d_out;

    cudaFuncSetAttribute(big_gemm_kernel, cudaFuncAttributeMaxDynamicSharedMemorySize, SMEM_BYTES);
    cudaFuncSetAttribute(small_mma_kernel, cudaFuncAttributeMaxDynamicSharedMemorySize, SSMEM_BYTES);

    int gm = N_NODES / BM;                     // 125
    int gsm = (N_NODES + SBM - 1) / SBM;       // 79

    prep_kernel<<<GB_END, 128>>>(nodes, emb, W1, W2);             // gather + W1^T + W2^T
    small_mma_kernel<<<gsm, 256, SSMEM_BYTES>>>(0);               // g_yTh = (x@W1)^T
    big_gemm_kernel<<<gm, 256, SMEM_BYTES>>>(adj, b1, nullptr);   // fused convert; -> g_h1h, g_adjh
    small_mma_kernel<<<gsm, 256, SSMEM_BYTES>>>(1);               // g_yTh = (h1@W2)^T
    big_gemm_kernel<<<gm, 256, SMEM_BYTES>>>(nullptr, b2, out);   // -> fp32 out
}